// round 10
// baseline (speedup 1.0000x reference)
#include <cuda_runtime.h>
#include <math.h>
#include <stdint.h>

// Flow_49546742727298: CNF Euler, exact divergence via analytic trace.
// R10: R9 tf32-MMA path + occupancy/chain surgery:
//   - bse/cj/b2 in per-CTA smem table (frees ~52 regs, launch_bounds(128,3))
//   - v relayout via warp shuffles (no SMEM roundtrip)
//   - h relayout stores vectorized (STS.64), conflict-free load pattern
//   - GEMM2 split into two 4-deep accumulator chains per nt

#define THREADS 128        // 4 warps per CTA, 64 samples per CTA
#define NSTEPS  2
#define BUFW    68         // smem row stride (floats) for 16x64 h tile

__device__ float g_c[65];  // c_j (64) + csum

__device__ __forceinline__ uint32_t tf32(float f) {
    uint32_t r; asm("cvt.rna.tf32.f32 %0, %1;" : "=r"(r) : "f"(f)); return r;
}
__device__ __forceinline__ float fast_tanh(float x) {
    float y; asm("tanh.approx.f32 %0, %1;" : "=f"(y) : "f"(x)); return y;
}
__device__ __forceinline__ void mma_tf32(float c[4], const uint32_t a[4],
                                         const uint32_t b0, const uint32_t b1) {
    asm("mma.sync.aligned.m16n8k8.row.col.f32.tf32.tf32.f32 "
        "{%0,%1,%2,%3}, {%4,%5,%6,%7}, {%8,%9}, {%0,%1,%2,%3};"
        : "+f"(c[0]), "+f"(c[1]), "+f"(c[2]), "+f"(c[3])
        : "r"(a[0]), "r"(a[1]), "r"(a[2]), "r"(a[3]), "r"(b0), "r"(b1));
}

// ---------- prep: c_j = sum_i W1[i][j]*W2[j][i], csum ----------
__global__ void prep_kernel(const float* __restrict__ W1,
                            const float* __restrict__ W2)
{
    const int j = threadIdx.x;   // 64
    float c = 0.f;
    #pragma unroll
    for (int i = 0; i < 16; i++)
        c += W1[i * 64 + j] * W2[j * 16 + i];
    g_c[j] = c;
    __syncthreads();
    if (j == 0) {
        float cs = 0.f;
        for (int k = 0; k < 64; k++) cs += g_c[k];
        g_c[64] = cs;
    }
}

// ---------- main ----------
__global__ void __launch_bounds__(THREADS, 3)
flow_kernel(const float* __restrict__ x0,
            const float* __restrict__ W1,
            const float* __restrict__ b1,
            const float* __restrict__ W2,
            const float* __restrict__ b2,
            float* __restrict__ out,
            int batch)
{
    __shared__ __align__(16) float hbuf[4][16 * BUFW];
    __shared__ __align__(16) float4 sconst[64];   // (bse0, bse1, c_j, 0)
    __shared__ __align__(8)  float  sb2s[16];

    const int tid  = threadIdx.x;
    const int lane = tid & 31;
    const int warp = tid >> 5;
    const int g    = lane >> 2;   // row-within-8
    const int tg   = lane & 3;    // thread-in-group
    const int gb   = lane & ~3;   // group base lane

    // ---- per-CTA constant table ----
    if (tid < 64) {
        const int j = tid;
        float bb = b1[j];
        float wt = W1[16 * 64 + j];
        sconst[j] = make_float4(bb, fmaf(0.5f, wt, bb), g_c[j], 0.f);
    } else if (tid < 80) {
        sb2s[tid - 64] = b2[tid - 64];
    }
    __syncthreads();

    const int row0 = blockIdx.x * 64 + warp * 16;
    if (row0 >= batch) return;
    float* buf = hbuf[warp];
    const float csum = __ldg(&g_c[64]);

    // ---- persistent weight fragments ----
    uint32_t w1f[8][2][2];
    #pragma unroll
    for (int nt = 0; nt < 8; nt++)
        #pragma unroll
        for (int kt = 0; kt < 2; kt++) {
            w1f[nt][kt][0] = tf32(W1[(8 * kt + tg)     * 64 + 8 * nt + g]);
            w1f[nt][kt][1] = tf32(W1[(8 * kt + tg + 4) * 64 + 8 * nt + g]);
        }
    uint32_t w2f[8][2][2];
    #pragma unroll
    for (int kt = 0; kt < 8; kt++)
        #pragma unroll
        for (int nt = 0; nt < 2; nt++) {
            w2f[kt][nt][0] = tf32(W2[(8 * kt + tg)     * 16 + 8 * nt + g]);
            w2f[kt][nt][1] = tf32(W2[(8 * kt + tg + 4) * 16 + 8 * nt + g]);
        }

    // ---- x A-fragments, exact fp32 ----
    float xe[2][4];
    #pragma unroll
    for (int kt = 0; kt < 2; kt++) {
        xe[kt][0] = x0[(size_t)(row0 + g)     * 16 + 8 * kt + tg];
        xe[kt][1] = x0[(size_t)(row0 + g + 8) * 16 + 8 * kt + tg];
        xe[kt][2] = x0[(size_t)(row0 + g)     * 16 + 8 * kt + tg + 4];
        xe[kt][3] = x0[(size_t)(row0 + g + 8) * 16 + 8 * kt + tg + 4];
    }

    const float dt = 0.5f;
    float logq0 = 0.f, logq1 = 0.f;

    #pragma unroll
    for (int s = 0; s < NSTEPS; s++) {
        uint32_t xa[2][4];
        #pragma unroll
        for (int kt = 0; kt < 2; kt++)
            #pragma unroll
            for (int i = 0; i < 4; i++)
                xa[kt][i] = tf32(xe[kt][i]);

        // ---- GEMM1: h_pre = x @ W1 + bse (bias/cj from smem table) ----
        float h[8][4];
        float cja[8], cjb[8];
        #pragma unroll
        for (int nt = 0; nt < 8; nt++) {
            float4 ca = sconst[8 * nt + 2 * tg];
            float4 cb = sconst[8 * nt + 2 * tg + 1];
            cja[nt] = ca.z; cjb[nt] = cb.z;
            float i0 = (s == 0) ? ca.x : ca.y;
            float i1 = (s == 0) ? cb.x : cb.y;
            h[nt][0] = i0; h[nt][1] = i1; h[nt][2] = i0; h[nt][3] = i1;
            mma_tf32(h[nt], xa[0], w1f[nt][0][0], w1f[nt][0][1]);
            mma_tf32(h[nt], xa[1], w1f[nt][1][0], w1f[nt][1][1]);
        }

        // ---- tanh + divergence partials ----
        float d0 = 0.f, d1 = 0.f;
        #pragma unroll
        for (int nt = 0; nt < 8; nt++) {
            h[nt][0] = fast_tanh(h[nt][0]);
            h[nt][1] = fast_tanh(h[nt][1]);
            h[nt][2] = fast_tanh(h[nt][2]);
            h[nt][3] = fast_tanh(h[nt][3]);
            d0 = fmaf(h[nt][0] * h[nt][0], cja[nt], d0);
            d0 = fmaf(h[nt][1] * h[nt][1], cjb[nt], d0);
            d1 = fmaf(h[nt][2] * h[nt][2], cja[nt], d1);
            d1 = fmaf(h[nt][3] * h[nt][3], cjb[nt], d1);
        }
        d0 += __shfl_xor_sync(0xffffffffu, d0, 1);
        d0 += __shfl_xor_sync(0xffffffffu, d0, 2);
        d1 += __shfl_xor_sync(0xffffffffu, d1, 1);
        d1 += __shfl_xor_sync(0xffffffffu, d1, 2);
        logq0 -= dt * (csum - d0);
        logq1 -= dt * (csum - d1);

        // ---- relayout h: C frags -> SMEM (STS.64) -> A frags ----
        #pragma unroll
        for (int nt = 0; nt < 8; nt++) {
            *(float2*)&buf[g * BUFW       + 8 * nt + 2 * tg] = make_float2(h[nt][0], h[nt][1]);
            *(float2*)&buf[(g + 8) * BUFW + 8 * nt + 2 * tg] = make_float2(h[nt][2], h[nt][3]);
        }
        __syncwarp();
        uint32_t ha[8][4];
        #pragma unroll
        for (int kt = 0; kt < 8; kt++) {
            ha[kt][0] = tf32(buf[g * BUFW       + 8 * kt + tg]);
            ha[kt][1] = tf32(buf[(g + 8) * BUFW + 8 * kt + tg]);
            ha[kt][2] = tf32(buf[g * BUFW       + 8 * kt + tg + 4]);
            ha[kt][3] = tf32(buf[(g + 8) * BUFW + 8 * kt + tg + 4]);
        }
        __syncwarp();

        // ---- GEMM2: v = h @ W2 + b2, two 4-deep chains per nt ----
        float v[2][4];
        #pragma unroll
        for (int nt = 0; nt < 2; nt++) {
            float2 bb = *(const float2*)&sb2s[8 * nt + 2 * tg];
            float va[4] = {bb.x, bb.y, bb.x, bb.y};
            float vb[4] = {0.f, 0.f, 0.f, 0.f};
            #pragma unroll
            for (int kt = 0; kt < 4; kt++)
                mma_tf32(va, ha[kt], w2f[kt][nt][0], w2f[kt][nt][1]);
            #pragma unroll
            for (int kt = 4; kt < 8; kt++)
                mma_tf32(vb, ha[kt], w2f[kt][nt][0], w2f[kt][nt][1]);
            #pragma unroll
            for (int i = 0; i < 4; i++) v[nt][i] = va[i] + vb[i];
        }

        // ---- v: C frag -> x A-layout via shuffles (no SMEM) ----
        #pragma unroll
        for (int kt = 0; kt < 2; kt++) {
            int src0 = gb | (tg >> 1);
            int src1 = gb | (2 + (tg >> 1));
            float e00 = __shfl_sync(0xffffffffu, v[kt][0], src0);
            float e01 = __shfl_sync(0xffffffffu, v[kt][1], src0);
            float e10 = __shfl_sync(0xffffffffu, v[kt][2], src0);
            float e11 = __shfl_sync(0xffffffffu, v[kt][3], src0);
            float f00 = __shfl_sync(0xffffffffu, v[kt][0], src1);
            float f01 = __shfl_sync(0xffffffffu, v[kt][1], src1);
            float f10 = __shfl_sync(0xffffffffu, v[kt][2], src1);
            float f11 = __shfl_sync(0xffffffffu, v[kt][3], src1);
            bool odd = (tg & 1);
            xe[kt][0] = fmaf(dt, odd ? e01 : e00, xe[kt][0]);  // row g,   col 8kt+tg
            xe[kt][1] = fmaf(dt, odd ? e11 : e10, xe[kt][1]);  // row g+8, col 8kt+tg
            xe[kt][2] = fmaf(dt, odd ? f01 : f00, xe[kt][2]);  // row g,   col 8kt+tg+4
            xe[kt][3] = fmaf(dt, odd ? f11 : f10, xe[kt][3]);  // row g+8, col 8kt+tg+4
        }
    }

    // ---- output ----
    #pragma unroll
    for (int kt = 0; kt < 2; kt++) {
        out[(size_t)(row0 + g)     * 16 + 8 * kt + tg]     = xe[kt][0];
        out[(size_t)(row0 + g + 8) * 16 + 8 * kt + tg]     = xe[kt][1];
        out[(size_t)(row0 + g)     * 16 + 8 * kt + tg + 4] = xe[kt][2];
        out[(size_t)(row0 + g + 8) * 16 + 8 * kt + tg + 4] = xe[kt][3];
    }
    if (tg == 0) {
        out[(size_t)batch * 16 + row0 + g]     = logq0;
        out[(size_t)batch * 16 + row0 + g + 8] = logq1;
    }
}

extern "C" void kernel_launch(void* const* d_in, const int* in_sizes, int n_in,
                              void* d_out, int out_size) {
    const float* x0 = (const float*)d_in[0];
    const float* W1 = (const float*)d_in[1];
    const float* b1 = (const float*)d_in[2];
    const float* W2 = (const float*)d_in[3];
    const float* b2 = (const float*)d_in[4];
    float* out = (float*)d_out;

    const int batch = in_sizes[0] / 16;      // 131072, divisible by 64
    prep_kernel<<<1, 64>>>(W1, W2);
    const int blocks = batch / 64;
    flow_kernel<<<blocks, THREADS>>>(x0, W1, b1, W2, b2, out, batch);
}

// round 11
// speedup vs baseline: 1.2434x; 1.2434x over previous
#include <cuda_runtime.h>
#include <math.h>
#include <stdint.h>

// Flow_49546742727298: CNF Euler, exact divergence via analytic trace.
// R11: persistent warps — grid = 3*148 CTAs (occupancy-exact), each warp
//      strides over 16-sample tiles reusing register-resident tf32 weight
//      fragments. Prep folded into the main kernel (c_j in table fill,
//      csum via warp reduce). Single kernel, single graph node.

#define THREADS 128        // 4 warps per CTA
#define NSTEPS  2
#define BUFW    68         // smem row stride (floats) for 16x64 h tile
#define GRID    (3 * 148)  // 3 CTAs/SM * 148 SMs

__device__ __forceinline__ uint32_t tf32(float f) {
    uint32_t r; asm("cvt.rna.tf32.f32 %0, %1;" : "=r"(r) : "f"(f)); return r;
}
__device__ __forceinline__ float fast_tanh(float x) {
    float y; asm("tanh.approx.f32 %0, %1;" : "=f"(y) : "f"(x)); return y;
}
__device__ __forceinline__ void mma_tf32(float c[4], const uint32_t a[4],
                                         const uint32_t b0, const uint32_t b1) {
    asm("mma.sync.aligned.m16n8k8.row.col.f32.tf32.tf32.f32 "
        "{%0,%1,%2,%3}, {%4,%5,%6,%7}, {%8,%9}, {%0,%1,%2,%3};"
        : "+f"(c[0]), "+f"(c[1]), "+f"(c[2]), "+f"(c[3])
        : "r"(a[0]), "r"(a[1]), "r"(a[2]), "r"(a[3]), "r"(b0), "r"(b1));
}

__global__ void __launch_bounds__(THREADS, 3)
flow_kernel(const float* __restrict__ x0,
            const float* __restrict__ W1,
            const float* __restrict__ b1,
            const float* __restrict__ W2,
            const float* __restrict__ b2,
            float* __restrict__ out,
            int batch)
{
    __shared__ __align__(16) float hbuf[4][16 * BUFW];
    __shared__ __align__(16) float4 sconst[64];   // (bse0, bse1, c_j, 0)
    __shared__ __align__(8)  float  sb2s[16];

    const int tid  = threadIdx.x;
    const int lane = tid & 31;
    const int warp = tid >> 5;
    const int g    = lane >> 2;   // row-within-8
    const int tg   = lane & 3;    // thread-in-group
    const int gb   = lane & ~3;   // group base lane

    // ---- per-CTA constant table (includes former prep kernel's c_j) ----
    if (tid < 64) {
        const int j = tid;
        float c = 0.f;
        #pragma unroll
        for (int i = 0; i < 16; i++)
            c += W1[i * 64 + j] * W2[j * 16 + i];
        float bb = b1[j];
        float wt = W1[16 * 64 + j];
        sconst[j] = make_float4(bb, fmaf(0.5f, wt, bb), c, 0.f);
    } else if (tid < 80) {
        sb2s[tid - 64] = b2[tid - 64];
    }
    __syncthreads();

    // csum: per-warp reduce over the 64 c_j entries (all lanes end with csum)
    float csum;
    {
        float cpart = sconst[lane].z + sconst[lane + 32].z;
        #pragma unroll
        for (int d = 16; d >= 1; d >>= 1)
            cpart += __shfl_xor_sync(0xffffffffu, cpart, d);
        csum = cpart;
    }

    // ---- persistent weight fragments (loop-invariant registers) ----
    uint32_t w1f[8][2][2];
    #pragma unroll
    for (int nt = 0; nt < 8; nt++)
        #pragma unroll
        for (int kt = 0; kt < 2; kt++) {
            w1f[nt][kt][0] = tf32(W1[(8 * kt + tg)     * 64 + 8 * nt + g]);
            w1f[nt][kt][1] = tf32(W1[(8 * kt + tg + 4) * 64 + 8 * nt + g]);
        }
    uint32_t w2f[8][2][2];
    #pragma unroll
    for (int kt = 0; kt < 8; kt++)
        #pragma unroll
        for (int nt = 0; nt < 2; nt++) {
            w2f[kt][nt][0] = tf32(W2[(8 * kt + tg)     * 16 + 8 * nt + g]);
            w2f[kt][nt][1] = tf32(W2[(8 * kt + tg + 4) * 16 + 8 * nt + g]);
        }

    float* buf = hbuf[warp];
    const float dt = 0.5f;

    // ---- tile loop: global warp id strides over 16-sample tiles ----
    const int gwarp   = blockIdx.x * 4 + warp;
    const int nwarps  = GRID * 4;
    const int ntiles  = batch >> 4;          // 16 samples per tile

    for (int wt = gwarp; wt < ntiles; wt += nwarps) {
        const int row0 = wt << 4;

        // x A-fragments, exact fp32
        float xe[2][4];
        #pragma unroll
        for (int kt = 0; kt < 2; kt++) {
            xe[kt][0] = x0[(size_t)(row0 + g)     * 16 + 8 * kt + tg];
            xe[kt][1] = x0[(size_t)(row0 + g + 8) * 16 + 8 * kt + tg];
            xe[kt][2] = x0[(size_t)(row0 + g)     * 16 + 8 * kt + tg + 4];
            xe[kt][3] = x0[(size_t)(row0 + g + 8) * 16 + 8 * kt + tg + 4];
        }

        float logq0 = 0.f, logq1 = 0.f;

        #pragma unroll
        for (int s = 0; s < NSTEPS; s++) {
            uint32_t xa[2][4];
            #pragma unroll
            for (int kt = 0; kt < 2; kt++)
                #pragma unroll
                for (int i = 0; i < 4; i++)
                    xa[kt][i] = tf32(xe[kt][i]);

            // GEMM1: h_pre = x @ W1 + bse
            float h[8][4];
            float cja[8], cjb[8];
            #pragma unroll
            for (int nt = 0; nt < 8; nt++) {
                float4 ca = sconst[8 * nt + 2 * tg];
                float4 cb = sconst[8 * nt + 2 * tg + 1];
                cja[nt] = ca.z; cjb[nt] = cb.z;
                float i0 = (s == 0) ? ca.x : ca.y;
                float i1 = (s == 0) ? cb.x : cb.y;
                h[nt][0] = i0; h[nt][1] = i1; h[nt][2] = i0; h[nt][3] = i1;
                mma_tf32(h[nt], xa[0], w1f[nt][0][0], w1f[nt][0][1]);
                mma_tf32(h[nt], xa[1], w1f[nt][1][0], w1f[nt][1][1]);
            }

            // tanh + divergence partials
            float d0 = 0.f, d1 = 0.f;
            #pragma unroll
            for (int nt = 0; nt < 8; nt++) {
                h[nt][0] = fast_tanh(h[nt][0]);
                h[nt][1] = fast_tanh(h[nt][1]);
                h[nt][2] = fast_tanh(h[nt][2]);
                h[nt][3] = fast_tanh(h[nt][3]);
                d0 = fmaf(h[nt][0] * h[nt][0], cja[nt], d0);
                d0 = fmaf(h[nt][1] * h[nt][1], cjb[nt], d0);
                d1 = fmaf(h[nt][2] * h[nt][2], cja[nt], d1);
                d1 = fmaf(h[nt][3] * h[nt][3], cjb[nt], d1);
            }
            d0 += __shfl_xor_sync(0xffffffffu, d0, 1);
            d0 += __shfl_xor_sync(0xffffffffu, d0, 2);
            d1 += __shfl_xor_sync(0xffffffffu, d1, 1);
            d1 += __shfl_xor_sync(0xffffffffu, d1, 2);
            logq0 -= dt * (csum - d0);
            logq1 -= dt * (csum - d1);

            // relayout h: C frags -> SMEM (STS.64) -> A frags
            #pragma unroll
            for (int nt = 0; nt < 8; nt++) {
                *(float2*)&buf[g * BUFW       + 8 * nt + 2 * tg] = make_float2(h[nt][0], h[nt][1]);
                *(float2*)&buf[(g + 8) * BUFW + 8 * nt + 2 * tg] = make_float2(h[nt][2], h[nt][3]);
            }
            __syncwarp();
            uint32_t ha[8][4];
            #pragma unroll
            for (int kt = 0; kt < 8; kt++) {
                ha[kt][0] = tf32(buf[g * BUFW       + 8 * kt + tg]);
                ha[kt][1] = tf32(buf[(g + 8) * BUFW + 8 * kt + tg]);
                ha[kt][2] = tf32(buf[g * BUFW       + 8 * kt + tg + 4]);
                ha[kt][3] = tf32(buf[(g + 8) * BUFW + 8 * kt + tg + 4]);
            }
            __syncwarp();

            // GEMM2: v = h @ W2 + b2, two 4-deep chains per nt
            float v[2][4];
            #pragma unroll
            for (int nt = 0; nt < 2; nt++) {
                float2 bb = *(const float2*)&sb2s[8 * nt + 2 * tg];
                float va[4] = {bb.x, bb.y, bb.x, bb.y};
                float vb[4] = {0.f, 0.f, 0.f, 0.f};
                #pragma unroll
                for (int kt = 0; kt < 4; kt++)
                    mma_tf32(va, ha[kt], w2f[kt][nt][0], w2f[kt][nt][1]);
                #pragma unroll
                for (int kt = 4; kt < 8; kt++)
                    mma_tf32(vb, ha[kt], w2f[kt][nt][0], w2f[kt][nt][1]);
                #pragma unroll
                for (int i = 0; i < 4; i++) v[nt][i] = va[i] + vb[i];
            }

            // v: C frag -> x A-layout via shuffles (no SMEM)
            #pragma unroll
            for (int kt = 0; kt < 2; kt++) {
                int src0 = gb | (tg >> 1);
                int src1 = gb | (2 + (tg >> 1));
                float e00 = __shfl_sync(0xffffffffu, v[kt][0], src0);
                float e01 = __shfl_sync(0xffffffffu, v[kt][1], src0);
                float e10 = __shfl_sync(0xffffffffu, v[kt][2], src0);
                float e11 = __shfl_sync(0xffffffffu, v[kt][3], src0);
                float f00 = __shfl_sync(0xffffffffu, v[kt][0], src1);
                float f01 = __shfl_sync(0xffffffffu, v[kt][1], src1);
                float f10 = __shfl_sync(0xffffffffu, v[kt][2], src1);
                float f11 = __shfl_sync(0xffffffffu, v[kt][3], src1);
                bool odd = (tg & 1);
                xe[kt][0] = fmaf(dt, odd ? e01 : e00, xe[kt][0]);
                xe[kt][1] = fmaf(dt, odd ? e11 : e10, xe[kt][1]);
                xe[kt][2] = fmaf(dt, odd ? f01 : f00, xe[kt][2]);
                xe[kt][3] = fmaf(dt, odd ? f11 : f10, xe[kt][3]);
            }
        }

        // output
        #pragma unroll
        for (int kt = 0; kt < 2; kt++) {
            out[(size_t)(row0 + g)     * 16 + 8 * kt + tg]     = xe[kt][0];
            out[(size_t)(row0 + g + 8) * 16 + 8 * kt + tg]     = xe[kt][1];
            out[(size_t)(row0 + g)     * 16 + 8 * kt + tg + 4] = xe[kt][2];
            out[(size_t)(row0 + g + 8) * 16 + 8 * kt + tg + 4] = xe[kt][3];
        }
        if (tg == 0) {
            out[(size_t)batch * 16 + row0 + g]     = logq0;
            out[(size_t)batch * 16 + row0 + g + 8] = logq1;
        }
    }
}

extern "C" void kernel_launch(void* const* d_in, const int* in_sizes, int n_in,
                              void* d_out, int out_size) {
    const float* x0 = (const float*)d_in[0];
    const float* W1 = (const float*)d_in[1];
    const float* b1 = (const float*)d_in[2];
    const float* W2 = (const float*)d_in[3];
    const float* b2 = (const float*)d_in[4];
    float* out = (float*)d_out;

    const int batch = in_sizes[0] / 16;      // 131072 (divisible by 16)
    flow_kernel<<<GRID, THREADS>>>(x0, W1, b1, W2, b2, out, batch);
}